// round 6
// baseline (speedup 1.0000x reference)
#include <cuda_runtime.h>
#include <cstdint>

#define Fdim 16
#define Sdim 512
#define Odim 32
#define Bdim 256
#define NCH  16            // shift chunks
#define SC   32            // shifts per chunk
#define BT   16            // batch rows per btile
#define NBT  16            // Bdim / BT
#define SF   (Sdim * Fdim) // floats per batch row

// Partial maxima scratch, pair-packed: [ch][b][g=8][o=32][p=2] = 8 MB (L2-resident)
__device__ float g_partial[NCH * Bdim * 8 * Odim * 2];
// Arrival counters per btile (zero-init; reducer self-resets -> replay-safe)
__device__ int g_cnt[NBT];

__device__ __forceinline__ float2 mul2(float2 a, float2 b) {
    float2 r;
    asm("mul.rn.f32x2 %0, %1, %2;"
        : "=l"(reinterpret_cast<unsigned long long&>(r))
        : "l"(reinterpret_cast<unsigned long long&>(a)),
          "l"(reinterpret_cast<unsigned long long&>(b)));
    return r;
}

// ---------------------------------------------------------------------------
// Fused kernel, 512 threads: o(32) x fg(4) x bgroup(4 of 4 rows).
// 96KB smem, 2 blocks/SM (32 warps). Last block per btile reduces.
// ---------------------------------------------------------------------------
__global__ __launch_bounds__(512, 2) void fused_kernel(
    const float* __restrict__ x, const float* __restrict__ W,
    const float* __restrict__ bias, float* __restrict__ out) {
    extern __shared__ float sm[];
    float* xs = sm;            // [BT][SC][Fdim] = 8192 floats (32 KB)
    float* ws = sm + 8192;     // [SC][8][Odim][2] = 16384 floats (64 KB)

    const int tid   = threadIdx.x;
    const int btile = blockIdx.x;
    const int ch    = blockIdx.y;

    // ---- stage x tile (coalesced float4) ----
    #pragma unroll
    for (int it = 0; it < 4; ++it) {
        int idx = tid + it * 512;              // 0..2047 float4s
        int b   = idx >> 7;                    // 128 float4 per row
        int t   = idx & 127;
        float4 v = *(const float4*)(x + (size_t)(btile * BT + b) * SF
                                      + ch * SC * Fdim + t * 4);
        *(float4*)(xs + b * (SC * Fdim) + t * 4) = v;
    }

    // ---- stage W chunk, transposed to [s][g][o][pair] (f = 2g+p) ----
    #pragma unroll
    for (int it = 0; it < 4; ++it) {
        int u  = tid + it * 512;               // 0..2047 units
        int s  = u >> 6;
        int g  = (u >> 3) & 7;
        int oq = u & 7;
        const float* wrow = W + ((size_t)(ch * SC + s) * Fdim + 2 * g) * Odim + 4 * oq;
        float4 a = *(const float4*)(wrow);          // f = 2g
        float4 b = *(const float4*)(wrow + Odim);   // f = 2g+1
        float2* dst = (float2*)(ws) + (s * 8 + g) * Odim + 4 * oq;
        dst[0] = make_float2(a.x, b.x);
        dst[1] = make_float2(a.y, b.y);
        dst[2] = make_float2(a.z, b.z);
        dst[3] = make_float2(a.w, b.w);
    }
    __syncthreads();

    // thread = (o lane, f-group fg -> pair {2fg, 2fg+1}, b-group of 4 rows)
    const int o  = tid & 31;
    const int fg = (tid >> 5) & 3;
    const int b0 = (tid >> 7) * 4;
    const int g0 = fg * 2;

    const float2* wp  = (const float2*)ws + g0 * Odim + o;
    const float4* xv4 = (const float4*)xs;

    const float NEG = __int_as_float(0xff800000);   // -inf
    float2 acc[4][2];
    #pragma unroll
    for (int i = 0; i < 4; ++i) {
        acc[i][0] = make_float2(NEG, NEG);
        acc[i][1] = make_float2(NEG, NEG);
    }

    #pragma unroll 4
    for (int s = 0; s < SC; ++s) {
        // conflict-free LDS.64: lanes stride-1 over o
        const float2 w01 = wp[s * (8 * Odim)];          // f = {2g0, 2g0+1}
        const float2 w23 = wp[s * (8 * Odim) + Odim];   // f = {2g0+2, 2g0+3}
        #pragma unroll
        for (int i = 0; i < 4; ++i) {
            // warp-uniform address -> broadcast LDS.128
            const float4 xv = xv4[((b0 + i) * SC + s) * 4 + fg];
            float2 p0 = mul2(make_float2(xv.x, xv.y), w01);
            float2 p1 = mul2(make_float2(xv.z, xv.w), w23);
            acc[i][0].x = fmaxf(acc[i][0].x, p0.x);
            acc[i][0].y = fmaxf(acc[i][0].y, p0.y);
            acc[i][1].x = fmaxf(acc[i][1].x, p1.x);
            acc[i][1].y = fmaxf(acc[i][1].y, p1.y);
        }
    }

    // ---- store partials, pair-packed, coalesced STG.64 over o ----
    #pragma unroll
    for (int i = 0; i < 4; ++i) {
        const int bglob = btile * BT + b0 + i;
        float2* dst = (float2*)g_partial + ((size_t)(ch * Bdim + bglob) * 8 + g0) * Odim + o;
        dst[0]    = acc[i][0];
        dst[Odim] = acc[i][1];
    }

    // ---- arrival: last chunk-block of this btile reduces ----
    __threadfence();
    __syncthreads();
    __shared__ int s_last;
    if (tid == 0) {
        int old = atomicAdd(&g_cnt[btile], 1);
        s_last = (old == NCH - 1);
        if (old == NCH - 1) g_cnt[btile] = 0;   // self-reset for graph replay
    }
    __syncthreads();
    if (!s_last) return;
    __threadfence();   // acquire

    // ---- tail (first 256 threads): thread = (row r, o-pair q), g-outer ----
    if (tid < 256) {
        const int r  = tid >> 4;          // 0..15
        const int q  = tid & 15;          // o-pair -> o = 2q, 2q+1
        const int bg = btile * BT + r;

        // per (ch, row): 128 contiguous float4; this thread reads q + 16*g
        const float4* base = (const float4*)g_partial + (size_t)bg * 128 + q;

        float s0 = 0.0f, s1 = 0.0f;
        #pragma unroll
        for (int g = 0; g < 8; ++g) {
            float4 m = make_float4(NEG, NEG, NEG, NEG);
            #pragma unroll 4
            for (int c = 0; c < NCH; ++c) {
                float4 v = __ldcg(base + (size_t)c * (Bdim * 128) + g * 16);
                m.x = fmaxf(m.x, v.x); m.y = fmaxf(m.y, v.y);
                m.z = fmaxf(m.z, v.z); m.w = fmaxf(m.w, v.w);
            }
            // float4 = [ (o,f=2g), (o,f=2g+1), (o+1,f=2g), (o+1,f=2g+1) ]
            s0 += m.x + m.y;
            s1 += m.z + m.w;
        }

        const float2 bv = *((const float2*)bias + q);
        float2 r2;
        r2.x = fmaxf(s0 + bv.x, 0.0f);
        r2.y = fmaxf(s1 + bv.y, 0.0f);
        *((float2*)(out + (size_t)bg * Odim) + q) = r2;
    }
}

// ---------------------------------------------------------------------------
extern "C" void kernel_launch(void* const* d_in, const int* in_sizes, int n_in,
                              void* d_out, int out_size) {
    const float* x    = (const float*)d_in[0];   // [256, 8192]
    const float* W    = (const float*)d_in[1];   // [8192, 32]
    const float* bias = (const float*)d_in[2];   // [32]
    float* out        = (float*)d_out;           // [256, 32]

    cudaFuncSetAttribute(fused_kernel, cudaFuncAttributeMaxDynamicSharedMemorySize,
                         96 * 1024);

    dim3 grid(NBT, NCH);
    fused_kernel<<<grid, 512, 96 * 1024>>>(x, W, bias, out);
}

// round 8
// speedup vs baseline: 1.5884x; 1.5884x over previous
#include <cuda_runtime.h>
#include <cstdint>

#define Fdim 16
#define Sdim 512
#define Odim 32
#define Bdim 256
#define NCH  16            // shift chunks
#define SC   32            // shifts per chunk
#define BT   16            // batch rows per btile
#define NBT  16            // Bdim / BT
#define SF   (Sdim * Fdim) // floats per batch row

// Partial maxima: [ch][b][fg=4][o=32] float4(f0..f3) = 8 MB (L2-resident)
__device__ float4 g_partial[NCH * Bdim * 4 * Odim];

__device__ __forceinline__ float2 mul2(float2 a, float2 b) {
    float2 r;
    asm("mul.rn.f32x2 %0, %1, %2;"
        : "=l"(reinterpret_cast<unsigned long long&>(r))
        : "l"(reinterpret_cast<unsigned long long&>(a)),
          "l"(reinterpret_cast<unsigned long long&>(b)));
    return r;
}

// ---------------------------------------------------------------------------
// Kernel 1: per (btile, chunk): partial[ch][b][f][o] = max_{s in chunk} x*W
// 256 threads = o(32) x fg(4) x bh(2, 8 rows each). 96KB smem, 2 blocks/SM.
// ---------------------------------------------------------------------------
__global__ __launch_bounds__(256, 2) void k1_partial(const float* __restrict__ x,
                                                     const float* __restrict__ W) {
    extern __shared__ float sm[];
    float*  xs = sm;             // [BT][SC][Fdim] = 8192 floats (32 KB)
    float4* ws = (float4*)(sm + 8192);  // [SC][4 fg][32 o] float4 = 64 KB

    const int tid   = threadIdx.x;
    const int btile = blockIdx.x;
    const int ch    = blockIdx.y;

    // ---- stage x tile (coalesced float4, natural layout) ----
    #pragma unroll
    for (int it = 0; it < 8; ++it) {
        int idx = tid + it * 256;              // 0..2047 float4s
        int b   = idx >> 7;                    // 128 float4 per row
        int t   = idx & 127;
        float4 v = *(const float4*)(x + (size_t)(btile * BT + b) * SF
                                      + ch * SC * Fdim + t * 4);
        *(float4*)(xs + b * (SC * Fdim) + t * 4) = v;
    }

    // ---- stage W: [s][f][o] -> smem [s][fg][o](f0..f3) ----
    // each unit = one (s, f) row of 4 o's; write scalar words into float4 slots
    #pragma unroll
    for (int it = 0; it < 8; ++it) {
        int u  = tid + it * 256;               // 0..2047 units
        int s  = u >> 6;                       // (s, f, oq) ; oq = group of 4 o
        int f  = (u >> 3) & 7;                 // 8 f per unit-pass; 2 f per unit
        int oq = u & 7;
        #pragma unroll
        for (int h = 0; h < 2; ++h) {          // f and f+8
            int ff = f + h * 8;
            float4 v = *(const float4*)(W + ((size_t)(ch * SC + s) * Fdim + ff) * Odim + 4 * oq);
            float* dst = (float*)(ws + ((s * 4 + (ff >> 2)) * Odim) + 4 * oq) + (ff & 3);
            dst[0]  = v.x;
            dst[4]  = v.y;
            dst[8]  = v.z;
            dst[12] = v.w;
        }
    }
    __syncthreads();

    // thread = (o lane, fg, bh -> 8 rows)
    const int o  = tid & 31;
    const int fg = (tid >> 5) & 3;
    const int b0 = (tid >> 7) * 8;

    const float4* wp  = ws + fg * Odim + o;        // + s*(4*Odim) per step
    const float4* xv4 = (const float4*)xs;          // ((b)*SC+s)*4 + fg

    const float NEG = __int_as_float(0xff800000);   // -inf
    float4 acc[8];
    #pragma unroll
    for (int i = 0; i < 8; ++i) acc[i] = make_float4(NEG, NEG, NEG, NEG);

    #pragma unroll 4
    for (int s = 0; s < SC; ++s) {
        // W: coalesced LDS.128, lanes stride 16B -> conflict-free
        const float4 wv = wp[s * (4 * Odim)];
        const float2 wxy = make_float2(wv.x, wv.y);
        const float2 wzw = make_float2(wv.z, wv.w);
        #pragma unroll
        for (int i = 0; i < 8; ++i) {
            // warp-uniform address -> broadcast LDS.128
            const float4 xv = xv4[((b0 + i) * SC + s) * 4 + fg];
            float2 p01 = mul2(make_float2(xv.x, xv.y), wxy);
            float2 p23 = mul2(make_float2(xv.z, xv.w), wzw);
            acc[i].x = fmaxf(acc[i].x, p01.x);
            acc[i].y = fmaxf(acc[i].y, p01.y);
            acc[i].z = fmaxf(acc[i].z, p23.x);
            acc[i].w = fmaxf(acc[i].w, p23.y);
        }
    }

    // ---- store partials: one coalesced STG.128 per row ----
    #pragma unroll
    for (int i = 0; i < 8; ++i) {
        const int bglob = btile * BT + b0 + i;
        g_partial[((size_t)(ch * Bdim + bglob) * 4 + fg) * Odim + o] = acc[i];
    }
}

// ---------------------------------------------------------------------------
// Kernel 2: out[b,o] = relu( bias[o] + sum_f max_ch partial )
// 256 blocks x 128 threads; thread = (fg, o): one float4 per chunk, coalesced.
// ---------------------------------------------------------------------------
__global__ __launch_bounds__(128) void k2_reduce(const float* __restrict__ bias,
                                                 float* __restrict__ out) {
    const int b  = blockIdx.x;
    const int t  = threadIdx.x;
    const int fg = t >> 5;
    const int o  = t & 31;

    const float NEG = __int_as_float(0xff800000);
    float4 m = make_float4(NEG, NEG, NEG, NEG);

    #pragma unroll
    for (int c = 0; c < NCH; ++c) {
        float4 v = __ldcg(&g_partial[(size_t)(c * Bdim + b) * 128 + t]);
        m.x = fmaxf(m.x, v.x); m.y = fmaxf(m.y, v.y);
        m.z = fmaxf(m.z, v.z); m.w = fmaxf(m.w, v.w);
    }

    __shared__ float red[4][Odim + 1];
    red[fg][o] = (m.x + m.y) + (m.z + m.w);
    __syncthreads();

    if (t < Odim) {
        float sum = bias[t] + red[0][t] + red[1][t] + red[2][t] + red[3][t];
        out[b * Odim + t] = fmaxf(sum, 0.0f);
    }
}

// ---------------------------------------------------------------------------
extern "C" void kernel_launch(void* const* d_in, const int* in_sizes, int n_in,
                              void* d_out, int out_size) {
    const float* x    = (const float*)d_in[0];   // [256, 8192]
    const float* W    = (const float*)d_in[1];   // [8192, 32]
    const float* bias = (const float*)d_in[2];   // [32]
    float* out        = (float*)d_out;           // [256, 32]

    cudaFuncSetAttribute(k1_partial, cudaFuncAttributeMaxDynamicSharedMemorySize,
                         96 * 1024);

    dim3 g1(NBT, NCH);
    k1_partial<<<g1, 256, 96 * 1024>>>(x, W);
    k2_reduce<<<Bdim, 128>>>(bias, out);
}

// round 10
// speedup vs baseline: 1.7178x; 1.0814x over previous
#include <cuda_runtime.h>
#include <cstdint>

#define Fdim 16
#define Sdim 512
#define Odim 32
#define Bdim 256
#define NCH  16            // shift chunks
#define SC   32            // shifts per chunk
#define BT   16            // batch rows per btile
#define NBT  16            // Bdim / BT
#define SF   (Sdim * Fdim) // floats per batch row

// Partial maxima: [ch][b][fg=4][o=32] float4(f0..f3) = 8 MB (L2-resident)
__device__ float4 g_partial[NCH * Bdim * 4 * Odim];

// ---------------------------------------------------------------------------
// Kernel 1: per (btile, chunk): partial[ch][b][f][o] = max_{s in chunk} x*W
// 256 threads = o(32) x fg(4) x bh(2 halves of 8 rows).
// Explicit 2-stage software pipeline: prefetch s+1 while computing s.
// ---------------------------------------------------------------------------
__global__ __launch_bounds__(256, 2) void k1_partial(const float* __restrict__ x,
                                                     const float* __restrict__ W) {
    extern __shared__ float sm[];
    float* xs = sm;            // [BT][SC][Fdim] = 8192 floats (32 KB), natural
    float* ws = sm + 8192;     // [SC][Fdim][Odim] = 16384 floats (64 KB), natural

    const int tid   = threadIdx.x;
    const int btile = blockIdx.x;
    const int ch    = blockIdx.y;

    // ---- stage x tile (coalesced float4, natural layout) ----
    #pragma unroll
    for (int it = 0; it < 8; ++it) {
        int idx = tid + it * 256;              // 0..2047 float4s
        int b   = idx >> 7;                    // 128 float4 per row
        int t   = idx & 127;
        float4 v = *(const float4*)(x + (size_t)(btile * BT + b) * SF
                                      + ch * SC * Fdim + t * 4);
        *(float4*)(xs + b * (SC * Fdim) + t * 4) = v;
    }

    // ---- stage W chunk (coalesced float4, natural layout, conflict-free) ----
    {
        const float4* wsrc = (const float4*)(W + (size_t)ch * SC * Fdim * Odim);
        #pragma unroll
        for (int it = 0; it < 16; ++it)
            ((float4*)ws)[tid + it * 256] = wsrc[tid + it * 256];
    }
    __syncthreads();

    // thread = (o lane, f-group fg, half bh -> 8 rows)
    const int o  = tid & 31;
    const int fg = (tid >> 5) & 3;
    const int b0 = (tid >> 7) * 8;
    const int f0 = fg * 4;

    // W scalar pointers: lanes stride-1 over o -> conflict-free (1 wf each)
    const float* wp  = ws + f0 * Odim + o;          // +s*(Fdim*Odim) per step
    const float4* xv4 = (const float4*)xs;           // ((b)*SC+s)*4 + fg

    const float NEG = __int_as_float(0xff800000);   // -inf
    float4 acc[8];
    #pragma unroll
    for (int i = 0; i < 8; ++i) acc[i] = make_float4(NEG, NEG, NEG, NEG);

    // ---- software-pipelined main loop (ping-pong buffers, unroll 2) ----
    float w0a, w1a, w2a, w3a, w0b, w1b, w2b, w3b;
    float4 xa[8], xb[8];

    // prologue: load s=0 into A
    w0a = wp[0 * Odim]; w1a = wp[1 * Odim]; w2a = wp[2 * Odim]; w3a = wp[3 * Odim];
    #pragma unroll
    for (int i = 0; i < 8; ++i) xa[i] = xv4[((b0 + i) * SC + 0) * 4 + fg];

    #pragma unroll
    for (int s = 0; s < SC; s += 2) {
        // prefetch s+1 into B
        {
            const float* wq = wp + (s + 1) * (Fdim * Odim);
            w0b = wq[0 * Odim]; w1b = wq[1 * Odim]; w2b = wq[2 * Odim]; w3b = wq[3 * Odim];
            #pragma unroll
            for (int i = 0; i < 8; ++i) xb[i] = xv4[((b0 + i) * SC + (s + 1)) * 4 + fg];
        }
        // compute s from A
        #pragma unroll
        for (int i = 0; i < 8; ++i) {
            acc[i].x = fmaxf(acc[i].x, xa[i].x * w0a);
            acc[i].y = fmaxf(acc[i].y, xa[i].y * w1a);
            acc[i].z = fmaxf(acc[i].z, xa[i].z * w2a);
            acc[i].w = fmaxf(acc[i].w, xa[i].w * w3a);
        }
        // prefetch s+2 into A (guarded; SC even)
        if (s + 2 < SC) {
            const float* wq = wp + (s + 2) * (Fdim * Odim);
            w0a = wq[0 * Odim]; w1a = wq[1 * Odim]; w2a = wq[2 * Odim]; w3a = wq[3 * Odim];
            #pragma unroll
            for (int i = 0; i < 8; ++i) xa[i] = xv4[((b0 + i) * SC + (s + 2)) * 4 + fg];
        }
        // compute s+1 from B
        #pragma unroll
        for (int i = 0; i < 8; ++i) {
            acc[i].x = fmaxf(acc[i].x, xb[i].x * w0b);
            acc[i].y = fmaxf(acc[i].y, xb[i].y * w1b);
            acc[i].z = fmaxf(acc[i].z, xb[i].z * w2b);
            acc[i].w = fmaxf(acc[i].w, xb[i].w * w3b);
        }
    }

    // ---- store partials: one coalesced STG.128 per row ----
    #pragma unroll
    for (int i = 0; i < 8; ++i) {
        const int bglob = btile * BT + b0 + i;
        g_partial[((size_t)(ch * Bdim + bglob) * 4 + fg) * Odim + o] = acc[i];
    }
}

// ---------------------------------------------------------------------------
// Kernel 2: out[b,o] = relu( bias[o] + sum_f max_ch partial )
// 256 blocks x 128 threads; thread = (fg, o): one float4 per chunk, coalesced.
// ---------------------------------------------------------------------------
__global__ __launch_bounds__(128) void k2_reduce(const float* __restrict__ bias,
                                                 float* __restrict__ out) {
    const int b  = blockIdx.x;
    const int t  = threadIdx.x;
    const int fg = t >> 5;
    const int o  = t & 31;

    const float NEG = __int_as_float(0xff800000);
    float4 m = make_float4(NEG, NEG, NEG, NEG);

    #pragma unroll
    for (int c = 0; c < NCH; ++c) {
        float4 v = __ldcg(&g_partial[(size_t)(c * Bdim + b) * 128 + t]);
        m.x = fmaxf(m.x, v.x); m.y = fmaxf(m.y, v.y);
        m.z = fmaxf(m.z, v.z); m.w = fmaxf(m.w, v.w);
    }

    __shared__ float red[4][Odim + 1];
    red[fg][o] = (m.x + m.y) + (m.z + m.w);
    __syncthreads();

    if (t < Odim) {
        float sum = bias[t] + red[0][t] + red[1][t] + red[2][t] + red[3][t];
        out[b * Odim + t] = fmaxf(sum, 0.0f);
    }
}

// ---------------------------------------------------------------------------
extern "C" void kernel_launch(void* const* d_in, const int* in_sizes, int n_in,
                              void* d_out, int out_size) {
    const float* x    = (const float*)d_in[0];   // [256, 8192]
    const float* W    = (const float*)d_in[1];   // [8192, 32]
    const float* bias = (const float*)d_in[2];   // [32]
    float* out        = (float*)d_out;           // [256, 32]

    cudaFuncSetAttribute(k1_partial, cudaFuncAttributeMaxDynamicSharedMemorySize,
                         96 * 1024);

    dim3 g1(NBT, NCH);
    k1_partial<<<g1, 256, 96 * 1024>>>(x, W);
    k2_reduce<<<Bdim, 128>>>(bias, out);
}